// round 12
// baseline (speedup 1.0000x reference)
#include <cuda_runtime.h>
#include <math.h>

#define BB 4
#define FF 1024
#define SS 2048
#define II 2048
#define EE 8
#define KW 5
#define OUTF 3072          // G*F
#define NT 8192            // B*S

typedef unsigned long long u64;

// ---------------- f32x2 helpers (packed fp32, exact .rn per lane) ----------------
__device__ __forceinline__ u64 dup2(float v) {
    u64 r; asm("mov.b64 %0, {%1, %2};" : "=l"(r) : "f"(v), "f"(v)); return r;
}
__device__ __forceinline__ void fma2(u64& d, u64 a, u64 b) {
    asm("fma.rn.f32x2 %0, %1, %2, %0;" : "+l"(d) : "l"(a), "l"(b));
}
__device__ __forceinline__ float2 upk2(u64 v) {
    float2 f; asm("mov.b64 {%0, %1}, %2;" : "=f"(f.x), "=f"(f.y) : "l"(v)); return f;
}
// 16B shared load -> two packed u64 (requires 16B alignment)
__device__ __forceinline__ void lds2(u64& a, u64& b, const void* p) {
    unsigned s = (unsigned)__cvta_generic_to_shared(p);
    asm volatile("ld.shared.v2.u64 {%0, %1}, [%2];" : "=l"(a), "=l"(b) : "r"(s));
}

// ---------------- scratch (static __device__, no allocation) ----------------
__device__ float g_xT[NT * FF];            // [token, F]
__device__ float g_h0tok[NT * II];         // [token, I]
__device__ float g_h0cs[BB * II * SS];     // [b, c, s] relu'd
__device__ float g_h1tok[NT * II];         // [token, I] relu'd
__device__ float g_h2tok[NT * OUTF];       // [token, 3F]
__device__ float g_w1t[KW * II * II];      // W1 transposed: [k][c][o]
__device__ int   g_cnt0[EE];
__device__ int   g_cnt2[EE];
__device__ int   g_list0[EE * NT];
__device__ int   g_list2[EE * NT];

// ---------------- utilities ----------------
__global__ void zero_counts_kernel() {
    if (threadIdx.x < EE) { g_cnt0[threadIdx.x] = 0; g_cnt2[threadIdx.x] = 0; }
}

// inp [B,F,S] -> xT [B*S, F]
__global__ void transpose_in_kernel(const float* __restrict__ in, float* __restrict__ xT) {
    __shared__ float tile[32][33];
    const int b = blockIdx.z;
    const int f0 = blockIdx.y * 32, s0 = blockIdx.x * 32;
    const int tx = threadIdx.x, ty = threadIdx.y;
    #pragma unroll
    for (int r = 0; r < 32; r += 8)
        tile[ty + r][tx] = in[((size_t)b * FF + f0 + ty + r) * SS + s0 + tx];
    __syncthreads();
    #pragma unroll
    for (int r = 0; r < 32; r += 8)
        xT[((size_t)b * SS + s0 + ty + r) * FF + f0 + tx] = tile[tx][ty + r];
}

// h0tok [B*S, I] -> h0cs [B, I, S] with relu
__global__ void transpose_relu_kernel(const float* __restrict__ h0tok, float* __restrict__ h0cs) {
    __shared__ float tile[32][33];
    const int b = blockIdx.z;
    const int i0 = blockIdx.y * 32, s0 = blockIdx.x * 32;
    const int tx = threadIdx.x, ty = threadIdx.y;
    #pragma unroll
    for (int r = 0; r < 32; r += 8)
        tile[ty + r][tx] = h0tok[((size_t)b * SS + s0 + ty + r) * II + i0 + tx];
    __syncthreads();
    #pragma unroll
    for (int r = 0; r < 32; r += 8)
        h0cs[((size_t)b * II + i0 + ty + r) * SS + s0 + tx] = fmaxf(tile[tx][ty + r], 0.0f);
}

// W1 [O][C][K] -> W1t [K][C][O]
__global__ void transpose_w1_kernel(const float* __restrict__ w1, float* __restrict__ wt) {
    __shared__ float tile[32][33];
    const int k  = blockIdx.z;
    const int c0 = blockIdx.y * 32, o0 = blockIdx.x * 32;
    const int tx = threadIdx.x, ty = threadIdx.y;
    #pragma unroll
    for (int r = 0; r < 32; r += 8)
        tile[ty + r][tx] = w1[((size_t)(o0 + ty + r) * II + c0 + tx) * KW + k];
    __syncthreads();
    #pragma unroll
    for (int r = 0; r < 32; r += 8)
        wt[((size_t)k * II + c0 + ty + r) * II + o0 + tx] = tile[tx][ty + r];
}

// ---------------- gating: logits + argmax + per-expert token lists ----------------
template<int KD>
__global__ __launch_bounds__(256) void gate_kernel(const float* __restrict__ X,
                                                   const float* __restrict__ Gw,
                                                   int* __restrict__ cnt,
                                                   int* __restrict__ list) {
    const int t = blockIdx.x;
    const float* x = X + (size_t)t * KD;
    float acc[EE];
    #pragma unroll
    for (int e = 0; e < EE; e++) acc[e] = 0.0f;
    for (int f = (threadIdx.x << 2); f < KD; f += 1024) {
        const float4 xv = *(const float4*)(x + f);
        #pragma unroll
        for (int e = 0; e < EE; e++) {
            const float4 g = *(const float4*)(Gw + e * KD + f);
            acc[e] += xv.x * g.x + xv.y * g.y + xv.z * g.z + xv.w * g.w;
        }
    }
    __shared__ float red[EE][256];
    #pragma unroll
    for (int e = 0; e < EE; e++) red[e][threadIdx.x] = acc[e];
    __syncthreads();
    for (int srt = 128; srt > 0; srt >>= 1) {
        if (threadIdx.x < srt) {
            #pragma unroll
            for (int e = 0; e < EE; e++) red[e][threadIdx.x] += red[e][threadIdx.x + srt];
        }
        __syncthreads();
    }
    if (threadIdx.x == 0) {
        int best = 0; float bv = red[0][0];
        #pragma unroll
        for (int e = 1; e < EE; e++) { const float v = red[e][0]; if (v > bv) { bv = v; best = e; } }
        const int pos = atomicAdd(&cnt[best], 1);
        list[best * NT + pos] = t;
    }
}

// ---------------- grouped expert GEMM: 128 tok x 128 n, BK=16, 256 thr, 8x8 (f32x2) ----
// R10-verbatim (proven): 33KB static smem; B reads as two contiguous 64B chunks.
template<int KD, int ND>
__global__ __launch_bounds__(256) void moe_gemm_kernel(const float* __restrict__ X,
                                                       const float* __restrict__ W,
                                                       const int* __restrict__ cnt,
                                                       const int* __restrict__ list,
                                                       float* __restrict__ out) {
    const int e = blockIdx.z;
    const int ce = cnt[e];
    const int m0 = blockIdx.y * 128;
    if (m0 >= ce) return;
    const int n0 = blockIdx.x * 128;
    const float* We = W + (size_t)e * KD * ND;

    __shared__ int   toks[128];
    __shared__ float As[2][16][132];
    __shared__ float Bs[2][16][128];

    const int tid = threadIdx.x;
    if (tid < 128) {
        const int m = m0 + tid;
        toks[tid] = list[e * NT + (m < ce ? m : ce - 1)];
    }
    __syncthreads();

    const int tx = tid & 15, ty = tid >> 4;
    const int la_m = tid >> 1;
    const int la_k = (tid & 1) << 3;
    const int lb_k = tid >> 4;
    const int lb_n = (tid & 15) << 3;
    const float* xrow = X + (size_t)toks[la_m] * KD + la_k;

    u64 acc2[8][4];
    #pragma unroll
    for (int i = 0; i < 8; i++)
        #pragma unroll
        for (int j = 0; j < 4; j++) acc2[i][j] = 0ull;

    {
        const float4 pa0 = *(const float4*)(xrow);
        const float4 pa1 = *(const float4*)(xrow + 4);
        const float* wp = We + (size_t)lb_k * ND + n0 + lb_n;
        const float4 pb0 = *(const float4*)wp;
        const float4 pb1 = *(const float4*)(wp + 4);
        const float pav[8] = {pa0.x, pa0.y, pa0.z, pa0.w, pa1.x, pa1.y, pa1.z, pa1.w};
        #pragma unroll
        for (int t = 0; t < 8; t++) As[0][la_k + t][la_m] = pav[t];
        *(float4*)&Bs[0][lb_k][lb_n]     = pb0;
        *(float4*)&Bs[0][lb_k][lb_n + 4] = pb1;
    }
    __syncthreads();

    int buf = 0;
    for (int k0 = 16; k0 < KD + 16; k0 += 16) {
        const bool nxt = (k0 < KD);
        float4 pa0, pa1, pb0, pb1;
        if (nxt) {
            pa0 = *(const float4*)(xrow + k0);
            pa1 = *(const float4*)(xrow + k0 + 4);
            const float* wp = We + (size_t)(k0 + lb_k) * ND + n0 + lb_n;
            pb0 = *(const float4*)wp;
            pb1 = *(const float4*)(wp + 4);
        }
        #pragma unroll 8
        for (int kk = 0; kk < 16; kk++) {
            const float4 a0 = *(const float4*)&As[buf][kk][ty << 3];
            const float4 a1 = *(const float4*)&As[buf][kk][(ty << 3) + 4];
            u64 bb0, bb1, bb2, bb3;
            lds2(bb0, bb1, &Bs[buf][kk][tx << 2]);
            lds2(bb2, bb3, &Bs[buf][kk][64 + (tx << 2)]);
            const float av[8] = {a0.x, a0.y, a0.z, a0.w, a1.x, a1.y, a1.z, a1.w};
            #pragma unroll
            for (int i = 0; i < 8; i++) {
                const u64 ad = dup2(av[i]);
                fma2(acc2[i][0], ad, bb0);
                fma2(acc2[i][1], ad, bb1);
                fma2(acc2[i][2], ad, bb2);
                fma2(acc2[i][3], ad, bb3);
            }
        }
        if (nxt) {
            const int nb = buf ^ 1;
            const float pav[8] = {pa0.x, pa0.y, pa0.z, pa0.w, pa1.x, pa1.y, pa1.z, pa1.w};
            #pragma unroll
            for (int t = 0; t < 8; t++) As[nb][la_k + t][la_m] = pav[t];
            *(float4*)&Bs[nb][lb_k][lb_n]     = pb0;
            *(float4*)&Bs[nb][lb_k][lb_n + 4] = pb1;
            __syncthreads();
            buf = nb;
        }
    }

    #pragma unroll
    for (int i = 0; i < 8; i++) {
        const int m = m0 + (ty << 3) + i;
        if (m < ce) {
            float* dst = out + (size_t)toks[(ty << 3) + i] * ND + n0;
            const float2 f0 = upk2(acc2[i][0]), f1 = upk2(acc2[i][1]);
            const float2 f2 = upk2(acc2[i][2]), f3 = upk2(acc2[i][3]);
            *(float4*)(dst + (tx << 2))      = make_float4(f0.x, f0.y, f1.x, f1.y);
            *(float4*)(dst + 64 + (tx << 2)) = make_float4(f2.x, f2.y, f3.x, f3.y);
        }
    }
}

// ---------------- causal conv: s-tile 128, o-tile 64, 256 thr, 4o x 8s per thread ------
// Wt: [K][C][O]; out[b,o,s] = sum_{c,k} Wt[k][c][o] * x[b,c,s+k-4]; relu; token-major out.
// o-tile 64 doubles tile count (N=2048); dynamic smem padded to 80KB to PIN occupancy at
// 2 blocks/SM (C=296): wave tail drops from ~16% (4 vs 3.46 waves) to ~1.2% (7 vs 6.92).
// R11 bugfix: W rows are 64 floats = 16 chunks -> row = idx>>4, ch = (idx&15)<<2.
#define CV_S 128
#define CV_O 64
#define CV_WS (80 * CV_O)                           // 5120 floats per buffer
#define CV_XS (16 * 136)                            // 2176 floats per buffer (132 used)
#define CV_SMEM 81920                               // inflated: forces 2 blocks/SM

__global__ __launch_bounds__(256, 2) void conv_kernel(const float* __restrict__ Wt,
                                                      const float* __restrict__ Xc,
                                                      float* __restrict__ Ytok) {
    extern __shared__ float csm[];
    float* Ws = csm;                                // [2][80][64]
    float* Xs = csm + 2 * CV_WS;                    // [2][16][136]

    const int s0 = blockIdx.x * CV_S;
    const int b  = blockIdx.y;
    const int o0 = blockIdx.z * CV_O;
    const int tid = threadIdx.x;
    const int sx = tid & 15;                        // s = s0 + 8*sx + 0..7
    const int oy = tid >> 4;                        // o = o0 + 4*oy + 0..3
    const float* xbase = Xc + (size_t)b * II * SS;

    u64 acc[2][8];                                  // [o-pair][s]
    #pragma unroll
    for (int p = 0; p < 2; p++)
        #pragma unroll
        for (int j = 0; j < 8; j++) acc[p][j] = 0ull;

    auto issue = [&](int c0, int bf) {
        #pragma unroll
        for (int t = 0; t < 5; t++) {               // W: 80 rows x 64 f = 1280 16B chunks
            const int idx = tid + t * 256;
            const int row = idx >> 4;               // 16 chunks per 64-float row (FIXED)
            const int ch  = (idx & 15) << 2;        // (FIXED)
            const int cc  = row / 5;
            const int k   = row - cc * 5;
            const float* src = Wt + ((size_t)k * II + (c0 + cc)) * II + o0 + ch;
            const unsigned dst = (unsigned)__cvta_generic_to_shared(
                Ws + bf * CV_WS + row * CV_O + ch);
            asm volatile("cp.async.cg.shared.global [%0], [%1], 16;\n" :: "r"(dst), "l"(src));
        }
        #pragma unroll
        for (int t = 0; t < 3; t++) {               // X: 16 x 132 f = 528 16B chunks
            const int idx = tid + t * 256;
            if (idx < 528) {
                const int cc = idx / 33;
                const int j4 = (idx - cc * 33) << 2;
                const int s  = s0 + j4 - 4;
                const float* src = xbase + (size_t)(c0 + cc) * SS + s;
                const unsigned dst = (unsigned)__cvta_generic_to_shared(
                    Xs + bf * CV_XS + cc * 136 + j4);
                const int pz = (s >= 0) ? 16 : 0;
                asm volatile("cp.async.cg.shared.global [%0], [%1], 16, %2;\n"
                             :: "r"(dst), "l"(src), "r"(pz));
            }
        }
        asm volatile("cp.async.commit_group;\n");
    };

    issue(0, 0);
    int buf = 0;
    for (int c0 = 0; c0 < II; c0 += 16) {
        const bool nxt = (c0 + 16 < II);
        if (nxt) issue(c0 + 16, buf ^ 1);
        if (nxt) asm volatile("cp.async.wait_group 1;\n");
        else     asm volatile("cp.async.wait_group 0;\n");
        __syncthreads();                            // Ws[buf]/Xs[buf] ready

        const float* Wsb = Ws + buf * CV_WS;
        const float* Xsb = Xs + buf * CV_XS;
        #pragma unroll 4
        for (int cc = 0; cc < 16; cc++) {
            const float* xr = Xsb + cc * 136 + (sx << 3);
            const float4 xa = *(const float4*)(xr);
            const float4 xb = *(const float4*)(xr + 4);
            const float4 xc = *(const float4*)(xr + 8);
            u64 xd[12];
            xd[0] = dup2(xa.x); xd[1]  = dup2(xa.y); xd[2]  = dup2(xa.z); xd[3]  = dup2(xa.w);
            xd[4] = dup2(xb.x); xd[5]  = dup2(xb.y); xd[6]  = dup2(xb.z); xd[7]  = dup2(xb.w);
            xd[8] = dup2(xc.x); xd[9]  = dup2(xc.y); xd[10] = dup2(xc.z); xd[11] = dup2(xc.w);
            #pragma unroll
            for (int k = 0; k < KW; k++) {
                u64 w0, w1;
                lds2(w0, w1, Wsb + (cc * 5 + k) * CV_O + (oy << 2));
                #pragma unroll
                for (int j = 0; j < 8; j++) {
                    fma2(acc[0][j], w0, xd[j + k]);
                    fma2(acc[1][j], w1, xd[j + k]);
                }
            }
        }
        __syncthreads();                            // all reads of Ws[buf]/Xs[buf] done
        buf ^= 1;                                   // before next issue overwrites it
    }

    // ---- relu + store (8 s-rows x 4 o) ----
    #pragma unroll
    for (int j = 0; j < 8; j++) {
        const int s = s0 + (sx << 3) + j;
        float* dst = Ytok + ((size_t)b * SS + s) * II + o0 + (oy << 2);
        const float2 f0 = upk2(acc[0][j]), f1 = upk2(acc[1][j]);
        *(float4*)dst = make_float4(fmaxf(f0.x, 0.f), fmaxf(f0.y, 0.f),
                                    fmaxf(f1.x, 0.f), fmaxf(f1.y, 0.f));
    }
}

// ---------------- cumsum / affine / norm ----------------
__global__ __launch_bounds__(256) void final_kernel(const float* __restrict__ H,
                                                    const float* __restrict__ divisor,
                                                    float* __restrict__ out) {
    const int t = blockIdx.x;
    const int b = t >> 11;
    const int s = t & (SS - 1);
    const float* h = H + (size_t)t * OUTF;
    const int tid = threadIdx.x;
    const int lane = tid & 31, wid = tid >> 5;

    const float4 d4 = *(const float4*)(h + (tid << 2));
    const float v0 = d4.x;
    const float v1 = v0 + d4.y;
    const float v2 = v1 + d4.z;
    const float v3 = v2 + d4.w;
    const float tsum = v3;

    float xsc = tsum;
    #pragma unroll
    for (int o = 1; o < 32; o <<= 1) {
        const float y = __shfl_up_sync(0xffffffffu, xsc, o);
        if (lane >= o) xsc += y;
    }
    __shared__ float wsum[8];
    __shared__ float woff[8];
    if (lane == 31) wsum[wid] = xsc;
    __syncthreads();
    if (tid == 0) { float r = 0.f; for (int w = 0; w < 8; w++) { woff[w] = r; r += wsum[w]; } }
    __syncthreads();
    const float off = woff[wid] + (xsc - tsum);

    const float invd = 1.0f / divisor[s];
    const float4 sc  = *(const float4*)(h + FF + (tid << 2));
    const float4 sh  = *(const float4*)(h + 2 * FF + (tid << 2));
    const float o0 = (v0 + off) * invd * sc.x + sh.x;
    const float o1 = (v1 + off) * invd * sc.y + sh.y;
    const float o2 = (v2 + off) * invd * sc.z + sh.z;
    const float o3 = (v3 + off) * invd * sc.w + sh.w;

    float s1 = o0 + o1 + o2 + o3;
    #pragma unroll
    for (int o = 16; o > 0; o >>= 1) s1 += __shfl_xor_sync(0xffffffffu, s1, o);
    __shared__ float r1[8];
    __shared__ float s_mean;
    if (lane == 0) r1[wid] = s1;
    __syncthreads();
    if (tid == 0) { float a = 0.f; for (int w = 0; w < 8; w++) a += r1[w]; s_mean = a * (1.0f / FF); }
    __syncthreads();
    const float mean = s_mean;

    const float c0 = o0 - mean, c1 = o1 - mean, c2 = o2 - mean, c3 = o3 - mean;
    float s2 = c0 * c0 + c1 * c1 + c2 * c2 + c3 * c3;
    #pragma unroll
    for (int o = 16; o > 0; o >>= 1) s2 += __shfl_xor_sync(0xffffffffu, s2, o);
    __shared__ float r2[8];
    __shared__ float s_scale;
    if (lane == 0) r2[wid] = s2;
    __syncthreads();
    if (tid == 0) {
        float a = 0.f;
        for (int w = 0; w < 8; w++) a += r2[w];
        const float denom = sqrtf(a) * (1.0f / 32.0f) + 1e-5f;
        s_scale = 0.25f / denom;
    }
    __syncthreads();
    const float k = s_scale;

    float* op = out + ((size_t)b * FF + (tid << 2)) * SS + s;
    op[0]              = c0 * k;
    op[SS]             = c1 * k;
    op[2 * (size_t)SS] = c2 * k;
    op[3 * (size_t)SS] = c3 * k;
}

// ---------------- launch ----------------
extern "C" void kernel_launch(void* const* d_in, const int* in_sizes, int n_in,
                              void* d_out, int out_size) {
    (void)in_sizes; (void)n_in; (void)out_size;
    const float* inp     = (const float*)d_in[0];
    const float* divisor = (const float*)d_in[1];
    const float* w0g     = (const float*)d_in[2];
    const float* w0      = (const float*)d_in[3];
    const float* w1      = (const float*)d_in[4];
    const float* w2g     = (const float*)d_in[5];
    const float* w2      = (const float*)d_in[6];
    float* out = (float*)d_out;

    float *xT, *h0tok, *h0cs, *h1tok, *h2tok, *w1t;
    int *cnt0, *cnt2, *list0, *list2;
    cudaGetSymbolAddress((void**)&xT,    g_xT);
    cudaGetSymbolAddress((void**)&h0tok, g_h0tok);
    cudaGetSymbolAddress((void**)&h0cs,  g_h0cs);
    cudaGetSymbolAddress((void**)&h1tok, g_h1tok);
    cudaGetSymbolAddress((void**)&h2tok, g_h2tok);
    cudaGetSymbolAddress((void**)&w1t,   g_w1t);
    cudaGetSymbolAddress((void**)&cnt0,  g_cnt0);
    cudaGetSymbolAddress((void**)&cnt2,  g_cnt2);
    cudaGetSymbolAddress((void**)&list0, g_list0);
    cudaGetSymbolAddress((void**)&list2, g_list2);

    static int attr_set = 0;
    if (!attr_set) {
        cudaFuncSetAttribute(conv_kernel, cudaFuncAttributeMaxDynamicSharedMemorySize,
                             CV_SMEM);
        attr_set = 1;
    }

    zero_counts_kernel<<<1, 32>>>();
    transpose_w1_kernel<<<dim3(II / 32, II / 32, KW), dim3(32, 8)>>>(w1, w1t);
    transpose_in_kernel<<<dim3(SS / 32, FF / 32, BB), dim3(32, 8)>>>(inp, xT);
    gate_kernel<FF><<<NT, 256>>>(xT, w0g, cnt0, list0);
    moe_gemm_kernel<FF, II><<<dim3(II / 128, NT / 128, EE), 256>>>(xT, w0, cnt0, list0, h0tok);
    transpose_relu_kernel<<<dim3(SS / 32, II / 32, BB), dim3(32, 8)>>>(h0tok, h0cs);
    conv_kernel<<<dim3(SS / CV_S, BB, II / CV_O), 256, CV_SMEM>>>(w1t, h0cs, h1tok);
    gate_kernel<II><<<NT, 256>>>(h1tok, w2g, cnt2, list2);
    moe_gemm_kernel<II, OUTF><<<dim3(OUTF / 128, NT / 128, EE), 256>>>(h1tok, w2, cnt2, list2, h2tok);
    final_kernel<<<NT, 256>>>(h2tok, divisor, out);
}

// round 13
// speedup vs baseline: 1.6660x; 1.6660x over previous
#include <cuda_runtime.h>
#include <math.h>

#define BB 4
#define FF 1024
#define SS 2048
#define II 2048
#define EE 8
#define KW 5
#define OUTF 3072          // G*F
#define NT 8192            // B*S

typedef unsigned long long u64;

// ---------------- f32x2 helpers (packed fp32, exact .rn per lane) ----------------
__device__ __forceinline__ u64 dup2(float v) {
    u64 r; asm("mov.b64 %0, {%1, %2};" : "=l"(r) : "f"(v), "f"(v)); return r;
}
__device__ __forceinline__ void fma2(u64& d, u64 a, u64 b) {
    asm("fma.rn.f32x2 %0, %1, %2, %0;" : "+l"(d) : "l"(a), "l"(b));
}
__device__ __forceinline__ float2 upk2(u64 v) {
    float2 f; asm("mov.b64 {%0, %1}, %2;" : "=f"(f.x), "=f"(f.y) : "l"(v)); return f;
}
// 16B shared load -> two packed u64 (requires 16B alignment)
__device__ __forceinline__ void lds2(u64& a, u64& b, const void* p) {
    unsigned s = (unsigned)__cvta_generic_to_shared(p);
    asm volatile("ld.shared.v2.u64 {%0, %1}, [%2];" : "=l"(a), "=l"(b) : "r"(s));
}

// ---------------- scratch (static __device__, no allocation) ----------------
__device__ float g_xT[NT * FF];            // [token, F]
__device__ float g_h0tok[NT * II];         // [token, I]
__device__ float g_h0cs[BB * II * SS];     // [b, c, s] relu'd
__device__ float g_h1tok[NT * II];         // [token, I] relu'd
__device__ float g_h2tok[NT * OUTF];       // [token, 3F]
__device__ float g_w1t[KW * II * II];      // W1 transposed: [k][c][o]
__device__ int   g_cnt0[EE];
__device__ int   g_cnt2[EE];
__device__ int   g_list0[EE * NT];
__device__ int   g_list2[EE * NT];

// ---------------- utilities ----------------
__global__ void zero_counts_kernel() {
    if (threadIdx.x < EE) { g_cnt0[threadIdx.x] = 0; g_cnt2[threadIdx.x] = 0; }
}

// inp [B,F,S] -> xT [B*S, F]
__global__ void transpose_in_kernel(const float* __restrict__ in, float* __restrict__ xT) {
    __shared__ float tile[32][33];
    const int b = blockIdx.z;
    const int f0 = blockIdx.y * 32, s0 = blockIdx.x * 32;
    const int tx = threadIdx.x, ty = threadIdx.y;
    #pragma unroll
    for (int r = 0; r < 32; r += 8)
        tile[ty + r][tx] = in[((size_t)b * FF + f0 + ty + r) * SS + s0 + tx];
    __syncthreads();
    #pragma unroll
    for (int r = 0; r < 32; r += 8)
        xT[((size_t)b * SS + s0 + ty + r) * FF + f0 + tx] = tile[tx][ty + r];
}

// h0tok [B*S, I] -> h0cs [B, I, S] with relu
__global__ void transpose_relu_kernel(const float* __restrict__ h0tok, float* __restrict__ h0cs) {
    __shared__ float tile[32][33];
    const int b = blockIdx.z;
    const int i0 = blockIdx.y * 32, s0 = blockIdx.x * 32;
    const int tx = threadIdx.x, ty = threadIdx.y;
    #pragma unroll
    for (int r = 0; r < 32; r += 8)
        tile[ty + r][tx] = h0tok[((size_t)b * SS + s0 + ty + r) * II + i0 + tx];
    __syncthreads();
    #pragma unroll
    for (int r = 0; r < 32; r += 8)
        h0cs[((size_t)b * II + i0 + ty + r) * SS + s0 + tx] = fmaxf(tile[tx][ty + r], 0.0f);
}

// W1 [O][C][K] -> W1t [K][C][O]
__global__ void transpose_w1_kernel(const float* __restrict__ w1, float* __restrict__ wt) {
    __shared__ float tile[32][33];
    const int k  = blockIdx.z;
    const int c0 = blockIdx.y * 32, o0 = blockIdx.x * 32;
    const int tx = threadIdx.x, ty = threadIdx.y;
    #pragma unroll
    for (int r = 0; r < 32; r += 8)
        tile[ty + r][tx] = w1[((size_t)(o0 + ty + r) * II + c0 + tx) * KW + k];
    __syncthreads();
    #pragma unroll
    for (int r = 0; r < 32; r += 8)
        wt[((size_t)k * II + c0 + ty + r) * II + o0 + tx] = tile[tx][ty + r];
}

// ---------------- gating: logits + argmax + per-expert token lists ----------------
template<int KD>
__global__ __launch_bounds__(256) void gate_kernel(const float* __restrict__ X,
                                                   const float* __restrict__ Gw,
                                                   int* __restrict__ cnt,
                                                   int* __restrict__ list) {
    const int t = blockIdx.x;
    const float* x = X + (size_t)t * KD;
    float acc[EE];
    #pragma unroll
    for (int e = 0; e < EE; e++) acc[e] = 0.0f;
    for (int f = (threadIdx.x << 2); f < KD; f += 1024) {
        const float4 xv = *(const float4*)(x + f);
        #pragma unroll
        for (int e = 0; e < EE; e++) {
            const float4 g = *(const float4*)(Gw + e * KD + f);
            acc[e] += xv.x * g.x + xv.y * g.y + xv.z * g.z + xv.w * g.w;
        }
    }
    __shared__ float red[EE][256];
    #pragma unroll
    for (int e = 0; e < EE; e++) red[e][threadIdx.x] = acc[e];
    __syncthreads();
    for (int srt = 128; srt > 0; srt >>= 1) {
        if (threadIdx.x < srt) {
            #pragma unroll
            for (int e = 0; e < EE; e++) red[e][threadIdx.x] += red[e][threadIdx.x + srt];
        }
        __syncthreads();
    }
    if (threadIdx.x == 0) {
        int best = 0; float bv = red[0][0];
        #pragma unroll
        for (int e = 1; e < EE; e++) { const float v = red[e][0]; if (v > bv) { bv = v; best = e; } }
        const int pos = atomicAdd(&cnt[best], 1);
        list[best * NT + pos] = t;
    }
}

// ---------------- grouped expert GEMM: 128 tok x 128 n, BK=16, 256 thr, 8x8 (f32x2) ----
// Proven R10 config: 33KB static smem; B reads as two contiguous 64B chunks.
template<int KD, int ND>
__global__ __launch_bounds__(256) void moe_gemm_kernel(const float* __restrict__ X,
                                                       const float* __restrict__ W,
                                                       const int* __restrict__ cnt,
                                                       const int* __restrict__ list,
                                                       float* __restrict__ out) {
    const int e = blockIdx.z;
    const int ce = cnt[e];
    const int m0 = blockIdx.y * 128;
    if (m0 >= ce) return;
    const int n0 = blockIdx.x * 128;
    const float* We = W + (size_t)e * KD * ND;

    __shared__ int   toks[128];
    __shared__ float As[2][16][132];
    __shared__ float Bs[2][16][128];

    const int tid = threadIdx.x;
    if (tid < 128) {
        const int m = m0 + tid;
        toks[tid] = list[e * NT + (m < ce ? m : ce - 1)];
    }
    __syncthreads();

    const int tx = tid & 15, ty = tid >> 4;
    const int la_m = tid >> 1;
    const int la_k = (tid & 1) << 3;
    const int lb_k = tid >> 4;
    const int lb_n = (tid & 15) << 3;
    const float* xrow = X + (size_t)toks[la_m] * KD + la_k;

    u64 acc2[8][4];
    #pragma unroll
    for (int i = 0; i < 8; i++)
        #pragma unroll
        for (int j = 0; j < 4; j++) acc2[i][j] = 0ull;

    {
        const float4 pa0 = *(const float4*)(xrow);
        const float4 pa1 = *(const float4*)(xrow + 4);
        const float* wp = We + (size_t)lb_k * ND + n0 + lb_n;
        const float4 pb0 = *(const float4*)wp;
        const float4 pb1 = *(const float4*)(wp + 4);
        const float pav[8] = {pa0.x, pa0.y, pa0.z, pa0.w, pa1.x, pa1.y, pa1.z, pa1.w};
        #pragma unroll
        for (int t = 0; t < 8; t++) As[0][la_k + t][la_m] = pav[t];
        *(float4*)&Bs[0][lb_k][lb_n]     = pb0;
        *(float4*)&Bs[0][lb_k][lb_n + 4] = pb1;
    }
    __syncthreads();

    int buf = 0;
    for (int k0 = 16; k0 < KD + 16; k0 += 16) {
        const bool nxt = (k0 < KD);
        float4 pa0, pa1, pb0, pb1;
        if (nxt) {
            pa0 = *(const float4*)(xrow + k0);
            pa1 = *(const float4*)(xrow + k0 + 4);
            const float* wp = We + (size_t)(k0 + lb_k) * ND + n0 + lb_n;
            pb0 = *(const float4*)wp;
            pb1 = *(const float4*)(wp + 4);
        }
        #pragma unroll 8
        for (int kk = 0; kk < 16; kk++) {
            const float4 a0 = *(const float4*)&As[buf][kk][ty << 3];
            const float4 a1 = *(const float4*)&As[buf][kk][(ty << 3) + 4];
            u64 bb0, bb1, bb2, bb3;
            lds2(bb0, bb1, &Bs[buf][kk][tx << 2]);
            lds2(bb2, bb3, &Bs[buf][kk][64 + (tx << 2)]);
            const float av[8] = {a0.x, a0.y, a0.z, a0.w, a1.x, a1.y, a1.z, a1.w};
            #pragma unroll
            for (int i = 0; i < 8; i++) {
                const u64 ad = dup2(av[i]);
                fma2(acc2[i][0], ad, bb0);
                fma2(acc2[i][1], ad, bb1);
                fma2(acc2[i][2], ad, bb2);
                fma2(acc2[i][3], ad, bb3);
            }
        }
        if (nxt) {
            const int nb = buf ^ 1;
            const float pav[8] = {pa0.x, pa0.y, pa0.z, pa0.w, pa1.x, pa1.y, pa1.z, pa1.w};
            #pragma unroll
            for (int t = 0; t < 8; t++) As[nb][la_k + t][la_m] = pav[t];
            *(float4*)&Bs[nb][lb_k][lb_n]     = pb0;
            *(float4*)&Bs[nb][lb_k][lb_n + 4] = pb1;
            __syncthreads();
            buf = nb;
        }
    }

    #pragma unroll
    for (int i = 0; i < 8; i++) {
        const int m = m0 + (ty << 3) + i;
        if (m < ce) {
            float* dst = out + (size_t)toks[(ty << 3) + i] * ND + n0;
            const float2 f0 = upk2(acc2[i][0]), f1 = upk2(acc2[i][1]);
            const float2 f2 = upk2(acc2[i][2]), f3 = upk2(acc2[i][3]);
            *(float4*)(dst + (tx << 2))      = make_float4(f0.x, f0.y, f1.x, f1.y);
            *(float4*)(dst + 64 + (tx << 2)) = make_float4(f2.x, f2.y, f3.x, f3.y);
        }
    }
}

// ---------------- causal conv: s-tile 128, o-tile 128, 256 thr, 8o x 8s per thread -----
// Proven R10 config: double-buffered cp.async, post-compute barrier (race-safe),
// 2 blocks x 16 warps/SM.
#define CV_S 128
#define CV_WS (80 * 128)                            // 10240 floats per buffer
#define CV_XS (16 * 136)                            // 2176 floats per buffer (132 used)
#define CV_SMEM ((2 * CV_WS + 2 * CV_XS) * 4)       // 99328 B

__global__ __launch_bounds__(256, 2) void conv_kernel(const float* __restrict__ Wt,
                                                      const float* __restrict__ Xc,
                                                      float* __restrict__ Ytok) {
    extern __shared__ float csm[];
    float* Ws = csm;                                // [2][80][128]
    float* Xs = csm + 2 * CV_WS;                    // [2][16][136]

    const int s0 = blockIdx.x * CV_S;
    const int b  = blockIdx.y;
    const int o0 = blockIdx.z * 128;
    const int tid = threadIdx.x;
    const int sx = tid & 15;                        // s = s0 + 8*sx + 0..7
    const int oy = tid >> 4;                        // o = o0 + 8*oy + 0..7
    const float* xbase = Xc + (size_t)b * II * SS;

    u64 acc[4][8];                                  // [o-pair][s]
    #pragma unroll
    for (int p = 0; p < 4; p++)
        #pragma unroll
        for (int j = 0; j < 8; j++) acc[p][j] = 0ull;

    auto issue = [&](int c0, int bf) {
        #pragma unroll
        for (int t = 0; t < 10; t++) {              // W: 80 rows x 128 f = 2560 16B chunks
            const int idx = tid + t * 256;
            const int row = idx >> 5;               // cc*5 + k
            const int ch  = (idx & 31) << 2;
            const int cc  = row / 5;
            const int k   = row - cc * 5;
            const float* src = Wt + ((size_t)k * II + (c0 + cc)) * II + o0 + ch;
            const unsigned dst = (unsigned)__cvta_generic_to_shared(
                Ws + bf * CV_WS + row * 128 + ch);
            asm volatile("cp.async.cg.shared.global [%0], [%1], 16;\n" :: "r"(dst), "l"(src));
        }
        #pragma unroll
        for (int t = 0; t < 3; t++) {               // X: 16 x 132 f = 528 16B chunks
            const int idx = tid + t * 256;
            if (idx < 528) {
                const int cc = idx / 33;
                const int j4 = (idx - cc * 33) << 2;
                const int s  = s0 + j4 - 4;
                const float* src = xbase + (size_t)(c0 + cc) * SS + s;
                const unsigned dst = (unsigned)__cvta_generic_to_shared(
                    Xs + bf * CV_XS + cc * 136 + j4);
                const int pz = (s >= 0) ? 16 : 0;
                asm volatile("cp.async.cg.shared.global [%0], [%1], 16, %2;\n"
                             :: "r"(dst), "l"(src), "r"(pz));
            }
        }
        asm volatile("cp.async.commit_group;\n");
    };

    issue(0, 0);
    int buf = 0;
    for (int c0 = 0; c0 < II; c0 += 16) {
        const bool nxt = (c0 + 16 < II);
        if (nxt) issue(c0 + 16, buf ^ 1);
        if (nxt) asm volatile("cp.async.wait_group 1;\n");
        else     asm volatile("cp.async.wait_group 0;\n");
        __syncthreads();                            // Ws[buf]/Xs[buf] ready

        const float* Wsb = Ws + buf * CV_WS;
        const float* Xsb = Xs + buf * CV_XS;
        #pragma unroll 4
        for (int cc = 0; cc < 16; cc++) {
            const float* xr = Xsb + cc * 136 + (sx << 3);
            const float4 xa = *(const float4*)(xr);
            const float4 xb = *(const float4*)(xr + 4);
            const float4 xc = *(const float4*)(xr + 8);
            u64 xd[12];
            xd[0] = dup2(xa.x); xd[1]  = dup2(xa.y); xd[2]  = dup2(xa.z); xd[3]  = dup2(xa.w);
            xd[4] = dup2(xb.x); xd[5]  = dup2(xb.y); xd[6]  = dup2(xb.z); xd[7]  = dup2(xb.w);
            xd[8] = dup2(xc.x); xd[9]  = dup2(xc.y); xd[10] = dup2(xc.z); xd[11] = dup2(xc.w);
            #pragma unroll
            for (int k = 0; k < KW; k++) {
                u64 w0, w1, w2, w3;
                const float* wp = Wsb + (cc * 5 + k) * 128 + (oy << 3);
                lds2(w0, w1, wp);
                lds2(w2, w3, wp + 4);
                #pragma unroll
                for (int j = 0; j < 8; j++) {
                    fma2(acc[0][j], w0, xd[j + k]);
                    fma2(acc[1][j], w1, xd[j + k]);
                    fma2(acc[2][j], w2, xd[j + k]);
                    fma2(acc[3][j], w3, xd[j + k]);
                }
            }
        }
        __syncthreads();                            // all reads of Ws[buf]/Xs[buf] done
        buf ^= 1;                                   // before next issue overwrites it
    }

    // ---- relu + store (8 s-rows x 8 o) ----
    #pragma unroll
    for (int j = 0; j < 8; j++) {
        const int s = s0 + (sx << 3) + j;
        float* dst = Ytok + ((size_t)b * SS + s) * II + o0 + (oy << 3);
        const float2 f0 = upk2(acc[0][j]), f1 = upk2(acc[1][j]);
        const float2 f2 = upk2(acc[2][j]), f3 = upk2(acc[3][j]);
        *(float4*)dst       = make_float4(fmaxf(f0.x, 0.f), fmaxf(f0.y, 0.f),
                                          fmaxf(f1.x, 0.f), fmaxf(f1.y, 0.f));
        *((float4*)dst + 1) = make_float4(fmaxf(f2.x, 0.f), fmaxf(f2.y, 0.f),
                                          fmaxf(f3.x, 0.f), fmaxf(f3.y, 0.f));
    }
}

// ---------------- cumsum / affine / norm ----------------
__global__ __launch_bounds__(256) void final_kernel(const float* __restrict__ H,
                                                    const float* __restrict__ divisor,
                                                    float* __restrict__ out) {
    const int t = blockIdx.x;
    const int b = t >> 11;
    const int s = t & (SS - 1);
    const float* h = H + (size_t)t * OUTF;
    const int tid = threadIdx.x;
    const int lane = tid & 31, wid = tid >> 5;

    const float4 d4 = *(const float4*)(h + (tid << 2));
    const float v0 = d4.x;
    const float v1 = v0 + d4.y;
    const float v2 = v1 + d4.z;
    const float v3 = v2 + d4.w;
    const float tsum = v3;

    float xsc = tsum;
    #pragma unroll
    for (int o = 1; o < 32; o <<= 1) {
        const float y = __shfl_up_sync(0xffffffffu, xsc, o);
        if (lane >= o) xsc += y;
    }
    __shared__ float wsum[8];
    __shared__ float woff[8];
    if (lane == 31) wsum[wid] = xsc;
    __syncthreads();
    if (tid == 0) { float r = 0.f; for (int w = 0; w < 8; w++) { woff[w] = r; r += wsum[w]; } }
    __syncthreads();
    const float off = woff[wid] + (xsc - tsum);

    const float invd = 1.0f / divisor[s];
    const float4 sc  = *(const float4*)(h + FF + (tid << 2));
    const float4 sh  = *(const float4*)(h + 2 * FF + (tid << 2));
    const float o0 = (v0 + off) * invd * sc.x + sh.x;
    const float o1 = (v1 + off) * invd * sc.y + sh.y;
    const float o2 = (v2 + off) * invd * sc.z + sh.z;
    const float o3 = (v3 + off) * invd * sc.w + sh.w;

    float s1 = o0 + o1 + o2 + o3;
    #pragma unroll
    for (int o = 16; o > 0; o >>= 1) s1 += __shfl_xor_sync(0xffffffffu, s1, o);
    __shared__ float r1[8];
    __shared__ float s_mean;
    if (lane == 0) r1[wid] = s1;
    __syncthreads();
    if (tid == 0) { float a = 0.f; for (int w = 0; w < 8; w++) a += r1[w]; s_mean = a * (1.0f / FF); }
    __syncthreads();
    const float mean = s_mean;

    const float c0 = o0 - mean, c1 = o1 - mean, c2 = o2 - mean, c3 = o3 - mean;
    float s2 = c0 * c0 + c1 * c1 + c2 * c2 + c3 * c3;
    #pragma unroll
    for (int o = 16; o > 0; o >>= 1) s2 += __shfl_xor_sync(0xffffffffu, s2, o);
    __shared__ float r2[8];
    __shared__ float s_scale;
    if (lane == 0) r2[wid] = s2;
    __syncthreads();
    if (tid == 0) {
        float a = 0.f;
        for (int w = 0; w < 8; w++) a += r2[w];
        const float denom = sqrtf(a) * (1.0f / 32.0f) + 1e-5f;
        s_scale = 0.25f / denom;
    }
    __syncthreads();
    const float k = s_scale;

    float* op = out + ((size_t)b * FF + (tid << 2)) * SS + s;
    op[0]              = c0 * k;
    op[SS]             = c1 * k;
    op[2 * (size_t)SS] = c2 * k;
    op[3 * (size_t)SS] = c3 * k;
}

// ---------------- launch ----------------
extern "C" void kernel_launch(void* const* d_in, const int* in_sizes, int n_in,
                              void* d_out, int out_size) {
    (void)in_sizes; (void)n_in; (void)out_size;
    const float* inp     = (const float*)d_in[0];
    const float* divisor = (const float*)d_in[1];
    const float* w0g     = (const float*)d_in[2];
    const float* w0      = (const float*)d_in[3];
    const float* w1      = (const float*)d_in[4];
    const float* w2g     = (const float*)d_in[5];
    const float* w2      = (const float*)d_in[6];
    float* out = (float*)d_out;

    float *xT, *h0tok, *h0cs, *h1tok, *h2tok, *w1t;
    int *cnt0, *cnt2, *list0, *list2;
    cudaGetSymbolAddress((void**)&xT,    g_xT);
    cudaGetSymbolAddress((void**)&h0tok, g_h0tok);
    cudaGetSymbolAddress((void**)&h0cs,  g_h0cs);
    cudaGetSymbolAddress((void**)&h1tok, g_h1tok);
    cudaGetSymbolAddress((void**)&h2tok, g_h2tok);
    cudaGetSymbolAddress((void**)&w1t,   g_w1t);
    cudaGetSymbolAddress((void**)&cnt0,  g_cnt0);
    cudaGetSymbolAddress((void**)&cnt2,  g_cnt2);
    cudaGetSymbolAddress((void**)&list0, g_list0);
    cudaGetSymbolAddress((void**)&list2, g_list2);

    static int attr_set = 0;
    if (!attr_set) {
        cudaFuncSetAttribute(conv_kernel, cudaFuncAttributeMaxDynamicSharedMemorySize,
                             CV_SMEM);
        attr_set = 1;
    }

    zero_counts_kernel<<<1, 32>>>();
    transpose_w1_kernel<<<dim3(II / 32, II / 32, KW), dim3(32, 8)>>>(w1, w1t);
    transpose_in_kernel<<<dim3(SS / 32, FF / 32, BB), dim3(32, 8)>>>(inp, xT);
    gate_kernel<FF><<<NT, 256>>>(xT, w0g, cnt0, list0);
    moe_gemm_kernel<FF, II><<<dim3(II / 128, NT / 128, EE), 256>>>(xT, w0, cnt0, list0, h0tok);
    transpose_relu_kernel<<<dim3(SS / 32, II / 32, BB), dim3(32, 8)>>>(h0tok, h0cs);
    conv_kernel<<<dim3(SS / CV_S, BB, II / 128), 256, CV_SMEM>>>(w1t, h0cs, h1tok);
    gate_kernel<II><<<NT, 256>>>(h1tok, w2g, cnt2, list2);
    moe_gemm_kernel<II, OUTF><<<dim3(OUTF / 128, NT / 128, EE), 256>>>(h1tok, w2, cnt2, list2, h2tok);
    final_kernel<<<NT, 256>>>(h2tok, divisor, out);
}

// round 14
// speedup vs baseline: 1.6739x; 1.0047x over previous
#include <cuda_runtime.h>
#include <math.h>

#define BB 4
#define FF 1024
#define SS 2048
#define II 2048
#define EE 8
#define KW 5
#define OUTF 3072          // G*F
#define NT 8192            // B*S

typedef unsigned long long u64;

// ---------------- f32x2 helpers (packed fp32, exact .rn per lane) ----------------
__device__ __forceinline__ u64 dup2(float v) {
    u64 r; asm("mov.b64 %0, {%1, %2};" : "=l"(r) : "f"(v), "f"(v)); return r;
}
__device__ __forceinline__ void fma2(u64& d, u64 a, u64 b) {
    asm("fma.rn.f32x2 %0, %1, %2, %0;" : "+l"(d) : "l"(a), "l"(b));
}
__device__ __forceinline__ float2 upk2(u64 v) {
    float2 f; asm("mov.b64 {%0, %1}, %2;" : "=f"(f.x), "=f"(f.y) : "l"(v)); return f;
}
// 16B shared load -> two packed u64 (requires 16B alignment)
__device__ __forceinline__ void lds2(u64& a, u64& b, const void* p) {
    unsigned s = (unsigned)__cvta_generic_to_shared(p);
    asm volatile("ld.shared.v2.u64 {%0, %1}, [%2];" : "=l"(a), "=l"(b) : "r"(s));
}

// ---------------- scratch (static __device__, no allocation) ----------------
__device__ float g_xT[NT * FF];            // [token, F]
__device__ float g_h0tok[NT * II];         // [token, I]
__device__ float g_h0cs[BB * II * SS];     // [b, c, s] relu'd
__device__ float g_h1tok[NT * II];         // [token, I] relu'd
__device__ float g_h2tok[NT * OUTF];       // [token, 3F]
__device__ float g_w1t[KW * II * II];      // W1 transposed: [k][c][o]
__device__ int   g_cnt0[EE];
__device__ int   g_cnt2[EE];
__device__ int   g_list0[EE * NT];
__device__ int   g_list2[EE * NT];

// ---------------- utilities ----------------
__global__ void zero_counts_kernel() {
    if (threadIdx.x < EE) { g_cnt0[threadIdx.x] = 0; g_cnt2[threadIdx.x] = 0; }
}

// inp [B,F,S] -> xT [B*S, F]
__global__ void transpose_in_kernel(const float* __restrict__ in, float* __restrict__ xT) {
    __shared__ float tile[32][33];
    const int b = blockIdx.z;
    const int f0 = blockIdx.y * 32, s0 = blockIdx.x * 32;
    const int tx = threadIdx.x, ty = threadIdx.y;
    #pragma unroll
    for (int r = 0; r < 32; r += 8)
        tile[ty + r][tx] = in[((size_t)b * FF + f0 + ty + r) * SS + s0 + tx];
    __syncthreads();
    #pragma unroll
    for (int r = 0; r < 32; r += 8)
        xT[((size_t)b * SS + s0 + ty + r) * FF + f0 + tx] = tile[tx][ty + r];
}

// h0tok [B*S, I] -> h0cs [B, I, S] with relu
__global__ void transpose_relu_kernel(const float* __restrict__ h0tok, float* __restrict__ h0cs) {
    __shared__ float tile[32][33];
    const int b = blockIdx.z;
    const int i0 = blockIdx.y * 32, s0 = blockIdx.x * 32;
    const int tx = threadIdx.x, ty = threadIdx.y;
    #pragma unroll
    for (int r = 0; r < 32; r += 8)
        tile[ty + r][tx] = h0tok[((size_t)b * SS + s0 + ty + r) * II + i0 + tx];
    __syncthreads();
    #pragma unroll
    for (int r = 0; r < 32; r += 8)
        h0cs[((size_t)b * II + i0 + ty + r) * SS + s0 + tx] = fmaxf(tile[tx][ty + r], 0.0f);
}

// W1 [O][C][K] -> W1t [K][C][O] — coalesced: each thread reads all 5 k of one (o,c)
// contiguously (20B dense; warp spans 640B fully used), writes 5 k-planes coalesced.
__global__ void transpose_w1_kernel(const float* __restrict__ w1, float* __restrict__ wt) {
    __shared__ float tile[KW][32][33];
    const int c0 = blockIdx.y * 32, o0 = blockIdx.x * 32;
    const int tx = threadIdx.x, ty = threadIdx.y;
    #pragma unroll
    for (int r = 0; r < 32; r += 8) {
        const float* p = w1 + ((size_t)(o0 + ty + r) * II + c0 + tx) * KW;
        #pragma unroll
        for (int k = 0; k < KW; k++)
            tile[k][ty + r][tx] = p[k];
    }
    __syncthreads();
    #pragma unroll
    for (int k = 0; k < KW; k++)
        #pragma unroll
        for (int r = 0; r < 32; r += 8)
            wt[((size_t)k * II + c0 + ty + r) * II + o0 + tx] = tile[k][tx][ty + r];
}

// ---------------- gating: logits + argmax + per-expert token lists ----------------
template<int KD>
__global__ __launch_bounds__(256) void gate_kernel(const float* __restrict__ X,
                                                   const float* __restrict__ Gw,
                                                   int* __restrict__ cnt,
                                                   int* __restrict__ list) {
    const int t = blockIdx.x;
    const float* x = X + (size_t)t * KD;
    float acc[EE];
    #pragma unroll
    for (int e = 0; e < EE; e++) acc[e] = 0.0f;
    for (int f = (threadIdx.x << 2); f < KD; f += 1024) {
        const float4 xv = *(const float4*)(x + f);
        #pragma unroll
        for (int e = 0; e < EE; e++) {
            const float4 g = *(const float4*)(Gw + e * KD + f);
            acc[e] += xv.x * g.x + xv.y * g.y + xv.z * g.z + xv.w * g.w;
        }
    }
    __shared__ float red[EE][256];
    #pragma unroll
    for (int e = 0; e < EE; e++) red[e][threadIdx.x] = acc[e];
    __syncthreads();
    for (int srt = 128; srt > 0; srt >>= 1) {
        if (threadIdx.x < srt) {
            #pragma unroll
            for (int e = 0; e < EE; e++) red[e][threadIdx.x] += red[e][threadIdx.x + srt];
        }
        __syncthreads();
    }
    if (threadIdx.x == 0) {
        int best = 0; float bv = red[0][0];
        #pragma unroll
        for (int e = 1; e < EE; e++) { const float v = red[e][0]; if (v > bv) { bv = v; best = e; } }
        const int pos = atomicAdd(&cnt[best], 1);
        list[best * NT + pos] = t;
    }
}

// ---------------- grouped expert GEMM: 128 tok x 128 n, BK=16, 256 thr, 8x8 (f32x2) ----
// Proven R10 config: 33KB static smem; B reads as two contiguous 64B chunks.
template<int KD, int ND>
__global__ __launch_bounds__(256) void moe_gemm_kernel(const float* __restrict__ X,
                                                       const float* __restrict__ W,
                                                       const int* __restrict__ cnt,
                                                       const int* __restrict__ list,
                                                       float* __restrict__ out) {
    const int e = blockIdx.z;
    const int ce = cnt[e];
    const int m0 = blockIdx.y * 128;
    if (m0 >= ce) return;
    const int n0 = blockIdx.x * 128;
    const float* We = W + (size_t)e * KD * ND;

    __shared__ int   toks[128];
    __shared__ float As[2][16][132];
    __shared__ float Bs[2][16][128];

    const int tid = threadIdx.x;
    if (tid < 128) {
        const int m = m0 + tid;
        toks[tid] = list[e * NT + (m < ce ? m : ce - 1)];
    }
    __syncthreads();

    const int tx = tid & 15, ty = tid >> 4;
    const int la_m = tid >> 1;
    const int la_k = (tid & 1) << 3;
    const int lb_k = tid >> 4;
    const int lb_n = (tid & 15) << 3;
    const float* xrow = X + (size_t)toks[la_m] * KD + la_k;

    u64 acc2[8][4];
    #pragma unroll
    for (int i = 0; i < 8; i++)
        #pragma unroll
        for (int j = 0; j < 4; j++) acc2[i][j] = 0ull;

    {
        const float4 pa0 = *(const float4*)(xrow);
        const float4 pa1 = *(const float4*)(xrow + 4);
        const float* wp = We + (size_t)lb_k * ND + n0 + lb_n;
        const float4 pb0 = *(const float4*)wp;
        const float4 pb1 = *(const float4*)(wp + 4);
        const float pav[8] = {pa0.x, pa0.y, pa0.z, pa0.w, pa1.x, pa1.y, pa1.z, pa1.w};
        #pragma unroll
        for (int t = 0; t < 8; t++) As[0][la_k + t][la_m] = pav[t];
        *(float4*)&Bs[0][lb_k][lb_n]     = pb0;
        *(float4*)&Bs[0][lb_k][lb_n + 4] = pb1;
    }
    __syncthreads();

    int buf = 0;
    for (int k0 = 16; k0 < KD + 16; k0 += 16) {
        const bool nxt = (k0 < KD);
        float4 pa0, pa1, pb0, pb1;
        if (nxt) {
            pa0 = *(const float4*)(xrow + k0);
            pa1 = *(const float4*)(xrow + k0 + 4);
            const float* wp = We + (size_t)(k0 + lb_k) * ND + n0 + lb_n;
            pb0 = *(const float4*)wp;
            pb1 = *(const float4*)(wp + 4);
        }
        #pragma unroll 8
        for (int kk = 0; kk < 16; kk++) {
            const float4 a0 = *(const float4*)&As[buf][kk][ty << 3];
            const float4 a1 = *(const float4*)&As[buf][kk][(ty << 3) + 4];
            u64 bb0, bb1, bb2, bb3;
            lds2(bb0, bb1, &Bs[buf][kk][tx << 2]);
            lds2(bb2, bb3, &Bs[buf][kk][64 + (tx << 2)]);
            const float av[8] = {a0.x, a0.y, a0.z, a0.w, a1.x, a1.y, a1.z, a1.w};
            #pragma unroll
            for (int i = 0; i < 8; i++) {
                const u64 ad = dup2(av[i]);
                fma2(acc2[i][0], ad, bb0);
                fma2(acc2[i][1], ad, bb1);
                fma2(acc2[i][2], ad, bb2);
                fma2(acc2[i][3], ad, bb3);
            }
        }
        if (nxt) {
            const int nb = buf ^ 1;
            const float pav[8] = {pa0.x, pa0.y, pa0.z, pa0.w, pa1.x, pa1.y, pa1.z, pa1.w};
            #pragma unroll
            for (int t = 0; t < 8; t++) As[nb][la_k + t][la_m] = pav[t];
            *(float4*)&Bs[nb][lb_k][lb_n]     = pb0;
            *(float4*)&Bs[nb][lb_k][lb_n + 4] = pb1;
            __syncthreads();
            buf = nb;
        }
    }

    #pragma unroll
    for (int i = 0; i < 8; i++) {
        const int m = m0 + (ty << 3) + i;
        if (m < ce) {
            float* dst = out + (size_t)toks[(ty << 3) + i] * ND + n0;
            const float2 f0 = upk2(acc2[i][0]), f1 = upk2(acc2[i][1]);
            const float2 f2 = upk2(acc2[i][2]), f3 = upk2(acc2[i][3]);
            *(float4*)(dst + (tx << 2))      = make_float4(f0.x, f0.y, f1.x, f1.y);
            *(float4*)(dst + 64 + (tx << 2)) = make_float4(f2.x, f2.y, f3.x, f3.y);
        }
    }
}

// ---------------- causal conv: s-tile 128, o-tile 128, 256 thr, 8o x 8s per thread -----
// Proven R10 config: double-buffered cp.async, post-compute barrier (race-safe),
// 2 blocks x 16 warps/SM.
#define CV_S 128
#define CV_WS (80 * 128)                            // 10240 floats per buffer
#define CV_XS (16 * 136)                            // 2176 floats per buffer (132 used)
#define CV_SMEM ((2 * CV_WS + 2 * CV_XS) * 4)       // 99328 B

__global__ __launch_bounds__(256, 2) void conv_kernel(const float* __restrict__ Wt,
                                                      const float* __restrict__ Xc,
                                                      float* __restrict__ Ytok) {
    extern __shared__ float csm[];
    float* Ws = csm;                                // [2][80][128]
    float* Xs = csm + 2 * CV_WS;                    // [2][16][136]

    const int s0 = blockIdx.x * CV_S;
    const int b  = blockIdx.y;
    const int o0 = blockIdx.z * 128;
    const int tid = threadIdx.x;
    const int sx = tid & 15;                        // s = s0 + 8*sx + 0..7
    const int oy = tid >> 4;                        // o = o0 + 8*oy + 0..7
    const float* xbase = Xc + (size_t)b * II * SS;

    u64 acc[4][8];                                  // [o-pair][s]
    #pragma unroll
    for (int p = 0; p < 4; p++)
        #pragma unroll
        for (int j = 0; j < 8; j++) acc[p][j] = 0ull;

    auto issue = [&](int c0, int bf) {
        #pragma unroll
        for (int t = 0; t < 10; t++) {              // W: 80 rows x 128 f = 2560 16B chunks
            const int idx = tid + t * 256;
            const int row = idx >> 5;               // cc*5 + k
            const int ch  = (idx & 31) << 2;
            const int cc  = row / 5;
            const int k   = row - cc * 5;
            const float* src = Wt + ((size_t)k * II + (c0 + cc)) * II + o0 + ch;
            const unsigned dst = (unsigned)__cvta_generic_to_shared(
                Ws + bf * CV_WS + row * 128 + ch);
            asm volatile("cp.async.cg.shared.global [%0], [%1], 16;\n" :: "r"(dst), "l"(src));
        }
        #pragma unroll
        for (int t = 0; t < 3; t++) {               // X: 16 x 132 f = 528 16B chunks
            const int idx = tid + t * 256;
            if (idx < 528) {
                const int cc = idx / 33;
                const int j4 = (idx - cc * 33) << 2;
                const int s  = s0 + j4 - 4;
                const float* src = xbase + (size_t)(c0 + cc) * SS + s;
                const unsigned dst = (unsigned)__cvta_generic_to_shared(
                    Xs + bf * CV_XS + cc * 136 + j4);
                const int pz = (s >= 0) ? 16 : 0;
                asm volatile("cp.async.cg.shared.global [%0], [%1], 16, %2;\n"
                             :: "r"(dst), "l"(src), "r"(pz));
            }
        }
        asm volatile("cp.async.commit_group;\n");
    };

    issue(0, 0);
    int buf = 0;
    for (int c0 = 0; c0 < II; c0 += 16) {
        const bool nxt = (c0 + 16 < II);
        if (nxt) issue(c0 + 16, buf ^ 1);
        if (nxt) asm volatile("cp.async.wait_group 1;\n");
        else     asm volatile("cp.async.wait_group 0;\n");
        __syncthreads();                            // Ws[buf]/Xs[buf] ready

        const float* Wsb = Ws + buf * CV_WS;
        const float* Xsb = Xs + buf * CV_XS;
        #pragma unroll 4
        for (int cc = 0; cc < 16; cc++) {
            const float* xr = Xsb + cc * 136 + (sx << 3);
            const float4 xa = *(const float4*)(xr);
            const float4 xb = *(const float4*)(xr + 4);
            const float4 xc = *(const float4*)(xr + 8);
            u64 xd[12];
            xd[0] = dup2(xa.x); xd[1]  = dup2(xa.y); xd[2]  = dup2(xa.z); xd[3]  = dup2(xa.w);
            xd[4] = dup2(xb.x); xd[5]  = dup2(xb.y); xd[6]  = dup2(xb.z); xd[7]  = dup2(xb.w);
            xd[8] = dup2(xc.x); xd[9]  = dup2(xc.y); xd[10] = dup2(xc.z); xd[11] = dup2(xc.w);
            #pragma unroll
            for (int k = 0; k < KW; k++) {
                u64 w0, w1, w2, w3;
                const float* wp = Wsb + (cc * 5 + k) * 128 + (oy << 3);
                lds2(w0, w1, wp);
                lds2(w2, w3, wp + 4);
                #pragma unroll
                for (int j = 0; j < 8; j++) {
                    fma2(acc[0][j], w0, xd[j + k]);
                    fma2(acc[1][j], w1, xd[j + k]);
                    fma2(acc[2][j], w2, xd[j + k]);
                    fma2(acc[3][j], w3, xd[j + k]);
                }
            }
        }
        __syncthreads();                            // all reads of Ws[buf]/Xs[buf] done
        buf ^= 1;                                   // before next issue overwrites it
    }

    // ---- relu + store (8 s-rows x 8 o) ----
    #pragma unroll
    for (int j = 0; j < 8; j++) {
        const int s = s0 + (sx << 3) + j;
        float* dst = Ytok + ((size_t)b * SS + s) * II + o0 + (oy << 3);
        const float2 f0 = upk2(acc[0][j]), f1 = upk2(acc[1][j]);
        const float2 f2 = upk2(acc[2][j]), f3 = upk2(acc[3][j]);
        *(float4*)dst       = make_float4(fmaxf(f0.x, 0.f), fmaxf(f0.y, 0.f),
                                          fmaxf(f1.x, 0.f), fmaxf(f1.y, 0.f));
        *((float4*)dst + 1) = make_float4(fmaxf(f2.x, 0.f), fmaxf(f2.y, 0.f),
                                          fmaxf(f3.x, 0.f), fmaxf(f3.y, 0.f));
    }
}

// ---------------- cumsum / affine / norm ----------------
__global__ __launch_bounds__(256) void final_kernel(const float* __restrict__ H,
                                                    const float* __restrict__ divisor,
                                                    float* __restrict__ out) {
    const int t = blockIdx.x;
    const int b = t >> 11;
    const int s = t & (SS - 1);
    const float* h = H + (size_t)t * OUTF;
    const int tid = threadIdx.x;
    const int lane = tid & 31, wid = tid >> 5;

    const float4 d4 = *(const float4*)(h + (tid << 2));
    const float v0 = d4.x;
    const float v1 = v0 + d4.y;
    const float v2 = v1 + d4.z;
    const float v3 = v2 + d4.w;
    const float tsum = v3;

    float xsc = tsum;
    #pragma unroll
    for (int o = 1; o < 32; o <<= 1) {
        const float y = __shfl_up_sync(0xffffffffu, xsc, o);
        if (lane >= o) xsc += y;
    }
    __shared__ float wsum[8];
    __shared__ float woff[8];
    if (lane == 31) wsum[wid] = xsc;
    __syncthreads();
    if (tid == 0) { float r = 0.f; for (int w = 0; w < 8; w++) { woff[w] = r; r += wsum[w]; } }
    __syncthreads();
    const float off = woff[wid] + (xsc - tsum);

    const float invd = 1.0f / divisor[s];
    const float4 sc  = *(const float4*)(h + FF + (tid << 2));
    const float4 sh  = *(const float4*)(h + 2 * FF + (tid << 2));
    const float o0 = (v0 + off) * invd * sc.x + sh.x;
    const float o1 = (v1 + off) * invd * sc.y + sh.y;
    const float o2 = (v2 + off) * invd * sc.z + sh.z;
    const float o3 = (v3 + off) * invd * sc.w + sh.w;

    float s1 = o0 + o1 + o2 + o3;
    #pragma unroll
    for (int o = 16; o > 0; o >>= 1) s1 += __shfl_xor_sync(0xffffffffu, s1, o);
    __shared__ float r1[8];
    __shared__ float s_mean;
    if (lane == 0) r1[wid] = s1;
    __syncthreads();
    if (tid == 0) { float a = 0.f; for (int w = 0; w < 8; w++) a += r1[w]; s_mean = a * (1.0f / FF); }
    __syncthreads();
    const float mean = s_mean;

    const float c0 = o0 - mean, c1 = o1 - mean, c2 = o2 - mean, c3 = o3 - mean;
    float s2 = c0 * c0 + c1 * c1 + c2 * c2 + c3 * c3;
    #pragma unroll
    for (int o = 16; o > 0; o >>= 1) s2 += __shfl_xor_sync(0xffffffffu, s2, o);
    __shared__ float r2[8];
    __shared__ float s_scale;
    if (lane == 0) r2[wid] = s2;
    __syncthreads();
    if (tid == 0) {
        float a = 0.f;
        for (int w = 0; w < 8; w++) a += r2[w];
        const float denom = sqrtf(a) * (1.0f / 32.0f) + 1e-5f;
        s_scale = 0.25f / denom;
    }
    __syncthreads();
    const float k = s_scale;

    float* op = out + ((size_t)b * FF + (tid << 2)) * SS + s;
    op[0]              = c0 * k;
    op[SS]             = c1 * k;
    op[2 * (size_t)SS] = c2 * k;
    op[3 * (size_t)SS] = c3 * k;
}

// ---------------- launch ----------------
extern "C" void kernel_launch(void* const* d_in, const int* in_sizes, int n_in,
                              void* d_out, int out_size) {
    (void)in_sizes; (void)n_in; (void)out_size;
    const float* inp     = (const float*)d_in[0];
    const float* divisor = (const float*)d_in[1];
    const float* w0g     = (const float*)d_in[2];
    const float* w0      = (const float*)d_in[3];
    const float* w1      = (const float*)d_in[4];
    const float* w2g     = (const float*)d_in[5];
    const float* w2      = (const float*)d_in[6];
    float* out = (float*)d_out;

    float *xT, *h0tok, *h0cs, *h1tok, *h2tok, *w1t;
    int *cnt0, *cnt2, *list0, *list2;
    cudaGetSymbolAddress((void**)&xT,    g_xT);
    cudaGetSymbolAddress((void**)&h0tok, g_h0tok);
    cudaGetSymbolAddress((void**)&h0cs,  g_h0cs);
    cudaGetSymbolAddress((void**)&h1tok, g_h1tok);
    cudaGetSymbolAddress((void**)&h2tok, g_h2tok);
    cudaGetSymbolAddress((void**)&w1t,   g_w1t);
    cudaGetSymbolAddress((void**)&cnt0,  g_cnt0);
    cudaGetSymbolAddress((void**)&cnt2,  g_cnt2);
    cudaGetSymbolAddress((void**)&list0, g_list0);
    cudaGetSymbolAddress((void**)&list2, g_list2);

    static int attr_set = 0;
    if (!attr_set) {
        cudaFuncSetAttribute(conv_kernel, cudaFuncAttributeMaxDynamicSharedMemorySize,
                             CV_SMEM);
        attr_set = 1;
    }

    zero_counts_kernel<<<1, 32>>>();
    transpose_w1_kernel<<<dim3(II / 32, II / 32), dim3(32, 8)>>>(w1, w1t);
    transpose_in_kernel<<<dim3(SS / 32, FF / 32, BB), dim3(32, 8)>>>(inp, xT);
    gate_kernel<FF><<<NT, 256>>>(xT, w0g, cnt0, list0);
    moe_gemm_kernel<FF, II><<<dim3(II / 128, NT / 128, EE), 256>>>(xT, w0, cnt0, list0, h0tok);
    transpose_relu_kernel<<<dim3(SS / 32, II / 32, BB), dim3(32, 8)>>>(h0tok, h0cs);
    conv_kernel<<<dim3(SS / CV_S, BB, II / 128), 256, CV_SMEM>>>(w1t, h0cs, h1tok);
    gate_kernel<II><<<NT, 256>>>(h1tok, w2g, cnt2, list2);
    moe_gemm_kernel<II, OUTF><<<dim3(OUTF / 128, NT / 128, EE), 256>>>(h1tok, w2, cnt2, list2, h2tok);
    final_kernel<<<NT, 256>>>(h2tok, divisor, out);
}

// round 15
// speedup vs baseline: 1.6781x; 1.0025x over previous
#include <cuda_runtime.h>
#include <math.h>

#define BB 4
#define FF 1024
#define SS 2048
#define II 2048
#define EE 8
#define KW 5
#define OUTF 3072          // G*F
#define NT 8192            // B*S

typedef unsigned long long u64;

// ---------------- f32x2 helpers (packed fp32, exact .rn per lane) ----------------
__device__ __forceinline__ u64 dup2(float v) {
    u64 r; asm("mov.b64 %0, {%1, %2};" : "=l"(r) : "f"(v), "f"(v)); return r;
}
__device__ __forceinline__ void fma2(u64& d, u64 a, u64 b) {
    asm("fma.rn.f32x2 %0, %1, %2, %0;" : "+l"(d) : "l"(a), "l"(b));
}
__device__ __forceinline__ float2 upk2(u64 v) {
    float2 f; asm("mov.b64 {%0, %1}, %2;" : "=f"(f.x), "=f"(f.y) : "l"(v)); return f;
}
// 16B shared load -> two packed u64 (requires 16B alignment)
__device__ __forceinline__ void lds2(u64& a, u64& b, const void* p) {
    unsigned s = (unsigned)__cvta_generic_to_shared(p);
    asm volatile("ld.shared.v2.u64 {%0, %1}, [%2];" : "=l"(a), "=l"(b) : "r"(s));
}

// ---------------- scratch (static __device__, no allocation) ----------------
__device__ float g_xT[NT * FF];            // [token, F]; reused as normalized-out scratch
__device__ float g_h0tok[NT * II];         // [token, I]
__device__ float g_h0cs[BB * II * SS];     // [b, c, s] relu'd
__device__ float g_h1tok[NT * II];         // [token, I] relu'd
__device__ float g_h2tok[NT * OUTF];       // [token, 3F]
__device__ float g_w1t[KW * II * II];      // W1 transposed: [k][c][o]
__device__ int   g_cnt0[EE];
__device__ int   g_cnt2[EE];
__device__ int   g_list0[EE * NT];
__device__ int   g_list2[EE * NT];

// ---------------- utilities ----------------
__global__ void zero_counts_kernel() {
    if (threadIdx.x < EE) { g_cnt0[threadIdx.x] = 0; g_cnt2[threadIdx.x] = 0; }
}

// inp [B,F,S] -> xT [B*S, F]
__global__ void transpose_in_kernel(const float* __restrict__ in, float* __restrict__ xT) {
    __shared__ float tile[32][33];
    const int b = blockIdx.z;
    const int f0 = blockIdx.y * 32, s0 = blockIdx.x * 32;
    const int tx = threadIdx.x, ty = threadIdx.y;
    #pragma unroll
    for (int r = 0; r < 32; r += 8)
        tile[ty + r][tx] = in[((size_t)b * FF + f0 + ty + r) * SS + s0 + tx];
    __syncthreads();
    #pragma unroll
    for (int r = 0; r < 32; r += 8)
        xT[((size_t)b * SS + s0 + ty + r) * FF + f0 + tx] = tile[tx][ty + r];
}

// hn [B*S, F] -> out [B,F,S]  (coalesced both sides)
__global__ void transpose_out_kernel(const float* __restrict__ hn, float* __restrict__ out) {
    __shared__ float tile[32][33];
    const int b = blockIdx.z;
    const int f0 = blockIdx.y * 32, s0 = blockIdx.x * 32;
    const int tx = threadIdx.x, ty = threadIdx.y;
    #pragma unroll
    for (int r = 0; r < 32; r += 8)
        tile[ty + r][tx] = hn[((size_t)b * SS + s0 + ty + r) * FF + f0 + tx];
    __syncthreads();
    #pragma unroll
    for (int r = 0; r < 32; r += 8)
        out[((size_t)b * FF + f0 + ty + r) * SS + s0 + tx] = tile[tx][ty + r];
}

// h0tok [B*S, I] -> h0cs [B, I, S] with relu
__global__ void transpose_relu_kernel(const float* __restrict__ h0tok, float* __restrict__ h0cs) {
    __shared__ float tile[32][33];
    const int b = blockIdx.z;
    const int i0 = blockIdx.y * 32, s0 = blockIdx.x * 32;
    const int tx = threadIdx.x, ty = threadIdx.y;
    #pragma unroll
    for (int r = 0; r < 32; r += 8)
        tile[ty + r][tx] = h0tok[((size_t)b * SS + s0 + ty + r) * II + i0 + tx];
    __syncthreads();
    #pragma unroll
    for (int r = 0; r < 32; r += 8)
        h0cs[((size_t)b * II + i0 + ty + r) * SS + s0 + tx] = fmaxf(tile[tx][ty + r], 0.0f);
}

// W1 [O][C][K] -> W1t [K][C][O] — coalesced (R14 proven)
__global__ void transpose_w1_kernel(const float* __restrict__ w1, float* __restrict__ wt) {
    __shared__ float tile[KW][32][33];
    const int c0 = blockIdx.y * 32, o0 = blockIdx.x * 32;
    const int tx = threadIdx.x, ty = threadIdx.y;
    #pragma unroll
    for (int r = 0; r < 32; r += 8) {
        const float* p = w1 + ((size_t)(o0 + ty + r) * II + c0 + tx) * KW;
        #pragma unroll
        for (int k = 0; k < KW; k++)
            tile[k][ty + r][tx] = p[k];
    }
    __syncthreads();
    #pragma unroll
    for (int k = 0; k < KW; k++)
        #pragma unroll
        for (int r = 0; r < 32; r += 8)
            wt[((size_t)k * II + c0 + ty + r) * II + o0 + tx] = tile[k][tx][ty + r];
}

// ---------------- gating: logits + argmax + per-expert token lists ----------------
template<int KD>
__global__ __launch_bounds__(256) void gate_kernel(const float* __restrict__ X,
                                                   const float* __restrict__ Gw,
                                                   int* __restrict__ cnt,
                                                   int* __restrict__ list) {
    const int t = blockIdx.x;
    const float* x = X + (size_t)t * KD;
    float acc[EE];
    #pragma unroll
    for (int e = 0; e < EE; e++) acc[e] = 0.0f;
    for (int f = (threadIdx.x << 2); f < KD; f += 1024) {
        const float4 xv = *(const float4*)(x + f);
        #pragma unroll
        for (int e = 0; e < EE; e++) {
            const float4 g = *(const float4*)(Gw + e * KD + f);
            acc[e] += xv.x * g.x + xv.y * g.y + xv.z * g.z + xv.w * g.w;
        }
    }
    __shared__ float red[EE][256];
    #pragma unroll
    for (int e = 0; e < EE; e++) red[e][threadIdx.x] = acc[e];
    __syncthreads();
    for (int srt = 128; srt > 0; srt >>= 1) {
        if (threadIdx.x < srt) {
            #pragma unroll
            for (int e = 0; e < EE; e++) red[e][threadIdx.x] += red[e][threadIdx.x + srt];
        }
        __syncthreads();
    }
    if (threadIdx.x == 0) {
        int best = 0; float bv = red[0][0];
        #pragma unroll
        for (int e = 1; e < EE; e++) { const float v = red[e][0]; if (v > bv) { bv = v; best = e; } }
        const int pos = atomicAdd(&cnt[best], 1);
        list[best * NT + pos] = t;
    }
}

// ---------------- grouped expert GEMM: 128 tok x 128 n, BK=16, 256 thr, 8x8 (f32x2) ----
// Proven R10 config: 33KB static smem; B reads as two contiguous 64B chunks.
template<int KD, int ND>
__global__ __launch_bounds__(256) void moe_gemm_kernel(const float* __restrict__ X,
                                                       const float* __restrict__ W,
                                                       const int* __restrict__ cnt,
                                                       const int* __restrict__ list,
                                                       float* __restrict__ out) {
    const int e = blockIdx.z;
    const int ce = cnt[e];
    const int m0 = blockIdx.y * 128;
    if (m0 >= ce) return;
    const int n0 = blockIdx.x * 128;
    const float* We = W + (size_t)e * KD * ND;

    __shared__ int   toks[128];
    __shared__ float As[2][16][132];
    __shared__ float Bs[2][16][128];

    const int tid = threadIdx.x;
    if (tid < 128) {
        const int m = m0 + tid;
        toks[tid] = list[e * NT + (m < ce ? m : ce - 1)];
    }
    __syncthreads();

    const int tx = tid & 15, ty = tid >> 4;
    const int la_m = tid >> 1;
    const int la_k = (tid & 1) << 3;
    const int lb_k = tid >> 4;
    const int lb_n = (tid & 15) << 3;
    const float* xrow = X + (size_t)toks[la_m] * KD + la_k;

    u64 acc2[8][4];
    #pragma unroll
    for (int i = 0; i < 8; i++)
        #pragma unroll
        for (int j = 0; j < 4; j++) acc2[i][j] = 0ull;

    {
        const float4 pa0 = *(const float4*)(xrow);
        const float4 pa1 = *(const float4*)(xrow + 4);
        const float* wp = We + (size_t)lb_k * ND + n0 + lb_n;
        const float4 pb0 = *(const float4*)wp;
        const float4 pb1 = *(const float4*)(wp + 4);
        const float pav[8] = {pa0.x, pa0.y, pa0.z, pa0.w, pa1.x, pa1.y, pa1.z, pa1.w};
        #pragma unroll
        for (int t = 0; t < 8; t++) As[0][la_k + t][la_m] = pav[t];
        *(float4*)&Bs[0][lb_k][lb_n]     = pb0;
        *(float4*)&Bs[0][lb_k][lb_n + 4] = pb1;
    }
    __syncthreads();

    int buf = 0;
    for (int k0 = 16; k0 < KD + 16; k0 += 16) {
        const bool nxt = (k0 < KD);
        float4 pa0, pa1, pb0, pb1;
        if (nxt) {
            pa0 = *(const float4*)(xrow + k0);
            pa1 = *(const float4*)(xrow + k0 + 4);
            const float* wp = We + (size_t)(k0 + lb_k) * ND + n0 + lb_n;
            pb0 = *(const float4*)wp;
            pb1 = *(const float4*)(wp + 4);
        }
        #pragma unroll 8
        for (int kk = 0; kk < 16; kk++) {
            const float4 a0 = *(const float4*)&As[buf][kk][ty << 3];
            const float4 a1 = *(const float4*)&As[buf][kk][(ty << 3) + 4];
            u64 bb0, bb1, bb2, bb3;
            lds2(bb0, bb1, &Bs[buf][kk][tx << 2]);
            lds2(bb2, bb3, &Bs[buf][kk][64 + (tx << 2)]);
            const float av[8] = {a0.x, a0.y, a0.z, a0.w, a1.x, a1.y, a1.z, a1.w};
            #pragma unroll
            for (int i = 0; i < 8; i++) {
                const u64 ad = dup2(av[i]);
                fma2(acc2[i][0], ad, bb0);
                fma2(acc2[i][1], ad, bb1);
                fma2(acc2[i][2], ad, bb2);
                fma2(acc2[i][3], ad, bb3);
            }
        }
        if (nxt) {
            const int nb = buf ^ 1;
            const float pav[8] = {pa0.x, pa0.y, pa0.z, pa0.w, pa1.x, pa1.y, pa1.z, pa1.w};
            #pragma unroll
            for (int t = 0; t < 8; t++) As[nb][la_k + t][la_m] = pav[t];
            *(float4*)&Bs[nb][lb_k][lb_n]     = pb0;
            *(float4*)&Bs[nb][lb_k][lb_n + 4] = pb1;
            __syncthreads();
            buf = nb;
        }
    }

    #pragma unroll
    for (int i = 0; i < 8; i++) {
        const int m = m0 + (ty << 3) + i;
        if (m < ce) {
            float* dst = out + (size_t)toks[(ty << 3) + i] * ND + n0;
            const float2 f0 = upk2(acc2[i][0]), f1 = upk2(acc2[i][1]);
            const float2 f2 = upk2(acc2[i][2]), f3 = upk2(acc2[i][3]);
            *(float4*)(dst + (tx << 2))      = make_float4(f0.x, f0.y, f1.x, f1.y);
            *(float4*)(dst + 64 + (tx << 2)) = make_float4(f2.x, f2.y, f3.x, f3.y);
        }
    }
}

// ---------------- causal conv: s-tile 128, o-tile 128, 256 thr, 8o x 8s per thread -----
// Proven R10 config: double-buffered cp.async, post-compute barrier (race-safe),
// 2 blocks x 16 warps/SM.
#define CV_S 128
#define CV_WS (80 * 128)                            // 10240 floats per buffer
#define CV_XS (16 * 136)                            // 2176 floats per buffer (132 used)
#define CV_SMEM ((2 * CV_WS + 2 * CV_XS) * 4)       // 99328 B

__global__ __launch_bounds__(256, 2) void conv_kernel(const float* __restrict__ Wt,
                                                      const float* __restrict__ Xc,
                                                      float* __restrict__ Ytok) {
    extern __shared__ float csm[];
    float* Ws = csm;                                // [2][80][128]
    float* Xs = csm + 2 * CV_WS;                    // [2][16][136]

    const int s0 = blockIdx.x * CV_S;
    const int b  = blockIdx.y;
    const int o0 = blockIdx.z * 128;
    const int tid = threadIdx.x;
    const int sx = tid & 15;                        // s = s0 + 8*sx + 0..7
    const int oy = tid >> 4;                        // o = o0 + 8*oy + 0..7
    const float* xbase = Xc + (size_t)b * II * SS;

    u64 acc[4][8];                                  // [o-pair][s]
    #pragma unroll
    for (int p = 0; p < 4; p++)
        #pragma unroll
        for (int j = 0; j < 8; j++) acc[p][j] = 0ull;

    auto issue = [&](int c0, int bf) {
        #pragma unroll
        for (int t = 0; t < 10; t++) {              // W: 80 rows x 128 f = 2560 16B chunks
            const int idx = tid + t * 256;
            const int row = idx >> 5;               // cc*5 + k
            const int ch  = (idx & 31) << 2;
            const int cc  = row / 5;
            const int k   = row - cc * 5;
            const float* src = Wt + ((size_t)k * II + (c0 + cc)) * II + o0 + ch;
            const unsigned dst = (unsigned)__cvta_generic_to_shared(
                Ws + bf * CV_WS + row * 128 + ch);
            asm volatile("cp.async.cg.shared.global [%0], [%1], 16;\n" :: "r"(dst), "l"(src));
        }
        #pragma unroll
        for (int t = 0; t < 3; t++) {               // X: 16 x 132 f = 528 16B chunks
            const int idx = tid + t * 256;
            if (idx < 528) {
                const int cc = idx / 33;
                const int j4 = (idx - cc * 33) << 2;
                const int s  = s0 + j4 - 4;
                const float* src = xbase + (size_t)(c0 + cc) * SS + s;
                const unsigned dst = (unsigned)__cvta_generic_to_shared(
                    Xs + bf * CV_XS + cc * 136 + j4);
                const int pz = (s >= 0) ? 16 : 0;
                asm volatile("cp.async.cg.shared.global [%0], [%1], 16, %2;\n"
                             :: "r"(dst), "l"(src), "r"(pz));
            }
        }
        asm volatile("cp.async.commit_group;\n");
    };

    issue(0, 0);
    int buf = 0;
    for (int c0 = 0; c0 < II; c0 += 16) {
        const bool nxt = (c0 + 16 < II);
        if (nxt) issue(c0 + 16, buf ^ 1);
        if (nxt) asm volatile("cp.async.wait_group 1;\n");
        else     asm volatile("cp.async.wait_group 0;\n");
        __syncthreads();                            // Ws[buf]/Xs[buf] ready

        const float* Wsb = Ws + buf * CV_WS;
        const float* Xsb = Xs + buf * CV_XS;
        #pragma unroll 4
        for (int cc = 0; cc < 16; cc++) {
            const float* xr = Xsb + cc * 136 + (sx << 3);
            const float4 xa = *(const float4*)(xr);
            const float4 xb = *(const float4*)(xr + 4);
            const float4 xc = *(const float4*)(xr + 8);
            u64 xd[12];
            xd[0] = dup2(xa.x); xd[1]  = dup2(xa.y); xd[2]  = dup2(xa.z); xd[3]  = dup2(xa.w);
            xd[4] = dup2(xb.x); xd[5]  = dup2(xb.y); xd[6]  = dup2(xb.z); xd[7]  = dup2(xb.w);
            xd[8] = dup2(xc.x); xd[9]  = dup2(xc.y); xd[10] = dup2(xc.z); xd[11] = dup2(xc.w);
            #pragma unroll
            for (int k = 0; k < KW; k++) {
                u64 w0, w1, w2, w3;
                const float* wp = Wsb + (cc * 5 + k) * 128 + (oy << 3);
                lds2(w0, w1, wp);
                lds2(w2, w3, wp + 4);
                #pragma unroll
                for (int j = 0; j < 8; j++) {
                    fma2(acc[0][j], w0, xd[j + k]);
                    fma2(acc[1][j], w1, xd[j + k]);
                    fma2(acc[2][j], w2, xd[j + k]);
                    fma2(acc[3][j], w3, xd[j + k]);
                }
            }
        }
        __syncthreads();                            // all reads of Ws[buf]/Xs[buf] done
        buf ^= 1;                                   // before next issue overwrites it
    }

    // ---- relu + store (8 s-rows x 8 o) ----
    #pragma unroll
    for (int j = 0; j < 8; j++) {
        const int s = s0 + (sx << 3) + j;
        float* dst = Ytok + ((size_t)b * SS + s) * II + o0 + (oy << 3);
        const float2 f0 = upk2(acc[0][j]), f1 = upk2(acc[1][j]);
        const float2 f2 = upk2(acc[2][j]), f3 = upk2(acc[3][j]);
        *(float4*)dst       = make_float4(fmaxf(f0.x, 0.f), fmaxf(f0.y, 0.f),
                                          fmaxf(f1.x, 0.f), fmaxf(f1.y, 0.f));
        *((float4*)dst + 1) = make_float4(fmaxf(f2.x, 0.f), fmaxf(f2.y, 0.f),
                                          fmaxf(f3.x, 0.f), fmaxf(f3.y, 0.f));
    }
}

// ---------------- cumsum / affine / norm — writes TOKEN-MAJOR (coalesced) --------------
__global__ __launch_bounds__(256) void final_kernel(const float* __restrict__ H,
                                                    const float* __restrict__ divisor,
                                                    float* __restrict__ hn) {
    const int t = blockIdx.x;
    const int s = t & (SS - 1);
    const float* h = H + (size_t)t * OUTF;
    const int tid = threadIdx.x;
    const int lane = tid & 31, wid = tid >> 5;

    const float4 d4 = *(const float4*)(h + (tid << 2));
    const float v0 = d4.x;
    const float v1 = v0 + d4.y;
    const float v2 = v1 + d4.z;
    const float v3 = v2 + d4.w;
    const float tsum = v3;

    float xsc = tsum;
    #pragma unroll
    for (int o = 1; o < 32; o <<= 1) {
        const float y = __shfl_up_sync(0xffffffffu, xsc, o);
        if (lane >= o) xsc += y;
    }
    __shared__ float wsum[8];
    __shared__ float woff[8];
    if (lane == 31) wsum[wid] = xsc;
    __syncthreads();
    if (tid == 0) { float r = 0.f; for (int w = 0; w < 8; w++) { woff[w] = r; r += wsum[w]; } }
    __syncthreads();
    const float off = woff[wid] + (xsc - tsum);

    const float invd = 1.0f / divisor[s];
    const float4 sc  = *(const float4*)(h + FF + (tid << 2));
    const float4 sh  = *(const float4*)(h + 2 * FF + (tid << 2));
    const float o0 = (v0 + off) * invd * sc.x + sh.x;
    const float o1 = (v1 + off) * invd * sc.y + sh.y;
    const float o2 = (v2 + off) * invd * sc.z + sh.z;
    const float o3 = (v3 + off) * invd * sc.w + sh.w;

    float s1 = o0 + o1 + o2 + o3;
    #pragma unroll
    for (int o = 16; o > 0; o >>= 1) s1 += __shfl_xor_sync(0xffffffffu, s1, o);
    __shared__ float r1[8];
    __shared__ float s_mean;
    if (lane == 0) r1[wid] = s1;
    __syncthreads();
    if (tid == 0) { float a = 0.f; for (int w = 0; w < 8; w++) a += r1[w]; s_mean = a * (1.0f / FF); }
    __syncthreads();
    const float mean = s_mean;

    const float c0 = o0 - mean, c1 = o1 - mean, c2 = o2 - mean, c3 = o3 - mean;
    float s2 = c0 * c0 + c1 * c1 + c2 * c2 + c3 * c3;
    #pragma unroll
    for (int o = 16; o > 0; o >>= 1) s2 += __shfl_xor_sync(0xffffffffu, s2, o);
    __shared__ float r2[8];
    __shared__ float s_scale;
    if (lane == 0) r2[wid] = s2;
    __syncthreads();
    if (tid == 0) {
        float a = 0.f;
        for (int w = 0; w < 8; w++) a += r2[w];
        const float denom = sqrtf(a) * (1.0f / 32.0f) + 1e-5f;
        s_scale = 0.25f / denom;
    }
    __syncthreads();
    const float k = s_scale;

    // token-major coalesced write: hn[t][f..f+3]
    *(float4*)(hn + (size_t)t * FF + (tid << 2)) =
        make_float4(c0 * k, c1 * k, c2 * k, c3 * k);
}

// ---------------- launch ----------------
extern "C" void kernel_launch(void* const* d_in, const int* in_sizes, int n_in,
                              void* d_out, int out_size) {
    (void)in_sizes; (void)n_in; (void)out_size;
    const float* inp     = (const float*)d_in[0];
    const float* divisor = (const float*)d_in[1];
    const float* w0g     = (const float*)d_in[2];
    const float* w0      = (const float*)d_in[3];
    const float* w1      = (const float*)d_in[4];
    const float* w2g     = (const float*)d_in[5];
    const float* w2      = (const float*)d_in[6];
    float* out = (float*)d_out;

    float *xT, *h0tok, *h0cs, *h1tok, *h2tok, *w1t;
    int *cnt0, *cnt2, *list0, *list2;
    cudaGetSymbolAddress((void**)&xT,    g_xT);
    cudaGetSymbolAddress((void**)&h0tok, g_h0tok);
    cudaGetSymbolAddress((void**)&h0cs,  g_h0cs);
    cudaGetSymbolAddress((void**)&h1tok, g_h1tok);
    cudaGetSymbolAddress((void**)&h2tok, g_h2tok);
    cudaGetSymbolAddress((void**)&w1t,   g_w1t);
    cudaGetSymbolAddress((void**)&cnt0,  g_cnt0);
    cudaGetSymbolAddress((void**)&cnt2,  g_cnt2);
    cudaGetSymbolAddress((void**)&list0, g_list0);
    cudaGetSymbolAddress((void**)&list2, g_list2);

    static int attr_set = 0;
    if (!attr_set) {
        cudaFuncSetAttribute(conv_kernel, cudaFuncAttributeMaxDynamicSharedMemorySize,
                             CV_SMEM);
        attr_set = 1;
    }

    zero_counts_kernel<<<1, 32>>>();
    transpose_w1_kernel<<<dim3(II / 32, II / 32), dim3(32, 8)>>>(w1, w1t);
    transpose_in_kernel<<<dim3(SS / 32, FF / 32, BB), dim3(32, 8)>>>(inp, xT);
    gate_kernel<FF><<<NT, 256>>>(xT, w0g, cnt0, list0);
    moe_gemm_kernel<FF, II><<<dim3(II / 128, NT / 128, EE), 256>>>(xT, w0, cnt0, list0, h0tok);
    transpose_relu_kernel<<<dim3(SS / 32, II / 32, BB), dim3(32, 8)>>>(h0tok, h0cs);
    conv_kernel<<<dim3(SS / CV_S, BB, II / 128), 256, CV_SMEM>>>(w1t, h0cs, h1tok);
    gate_kernel<II><<<NT, 256>>>(h1tok, w2g, cnt2, list2);
    moe_gemm_kernel<II, OUTF><<<dim3(OUTF / 128, NT / 128, EE), 256>>>(h1tok, w2, cnt2, list2, h2tok);
    // final: normalized values token-major into xT (dead after moe0), then coalesced
    // transpose to the harness layout [B,F,S]
    final_kernel<<<NT, 256>>>(h2tok, divisor, xT);
    transpose_out_kernel<<<dim3(SS / 32, FF / 32, BB), dim3(32, 8)>>>(xT, out);
}